// round 6
// baseline (speedup 1.0000x reference)
#include <cuda_runtime.h>
#include <cstdint>

// DiagonalSISOCell: V=100000, D=64, N=16
// out[v,d,q] = sum_n ( exp(delta_v*A[d,n])*state[v,d,n] + delta_v*B[d,n]*x[v,d] ) * C[d,n,q]
// delta_v = softplus(x[v,:] @ w_delta + b_delta)

#define V_TOK 100000
#define VPAD  100224
#define LOG2E 1.4426950408889634f

__device__ float g_delta[VPAD];
__device__ float g_dxT[64 * VPAD];   // dxT[d][v] = delta_v * x[v,d]

// ---- smem layout (floats) ----------------------------------------------------
#define PITCH4  33                   // float4 pitch per token row (132 floats)
#define OFF_C   0                    // C_s[8][256]
#define OFF_AB  2048                 // AB_s[8][16] float2
#define OFF_TILE 2304                // tile[64][132]
#define SMEM_FLOATS (2304 + 64 * 132)  // 10752 floats = 43008 B

// ---------------------------------------------------------------------------
__device__ __forceinline__ float2 ffma2(float2 a, float2 b, float2 c) {
    float2 r;
    asm("fma.rn.f32x2 %0, %1, %2, %3;"
        : "=l"(*reinterpret_cast<unsigned long long*>(&r))
        : "l"(*reinterpret_cast<unsigned long long*>(&a)),
          "l"(*reinterpret_cast<unsigned long long*>(&b)),
          "l"(*reinterpret_cast<unsigned long long*>(&c)));
    return r;
}
__device__ __forceinline__ float ex2_approx(float x) {
    float r; asm("ex2.approx.f32 %0, %1;" : "=f"(r) : "f"(x)); return r;
}

// ---------------------------------------------------------------------------
// Kernel 1: per 32-token block — delta[v] (softplus) and transposed
// dxT[d][v] = delta_v * x[v,d], coalesced reads AND writes.
// ---------------------------------------------------------------------------
__global__ void __launch_bounds__(128)
delta_kernel(const float* __restrict__ x,
             const float* __restrict__ w,
             const float* __restrict__ b)
{
    __shared__ float xs[32 * 65];
    __shared__ float ws[64];
    __shared__ float ds[32];

    const int tid = threadIdx.x;
    const int v0  = blockIdx.x * 32;

    if (tid < 64) ws[tid] = w[tid];

#pragma unroll
    for (int j = 0; j < 16; j++) {
        int idx = j * 128 + tid;
        int row = idx >> 6, col = idx & 63;
        xs[row * 65 + col] = x[(size_t)v0 * 64 + idx];
    }
    __syncthreads();

    {
        int t = tid >> 2, sub = tid & 3;
        float s = 0.f;
        const float* xr = xs + t * 65 + sub * 16;
        const float* wr = ws + sub * 16;
#pragma unroll
        for (int k = 0; k < 16; k++) s = fmaf(xr[k], wr[k], s);
        s += __shfl_xor_sync(0xffffffffu, s, 1);
        s += __shfl_xor_sync(0xffffffffu, s, 2);
        if (sub == 0) {
            float tt = s + b[0];
            ds[t] = fmaxf(tt, 0.0f) + log1pf(expf(-fabsf(tt)));
        }
    }
    __syncthreads();

    if (tid < 32) g_delta[v0 + tid] = ds[tid];

#pragma unroll
    for (int j = 0; j < 16; j++) {
        int d = j * 4 + (tid >> 5);
        int t = tid & 31;
        g_dxT[(size_t)d * VPAD + v0 + t] = ds[t] * xs[t * 65 + d];
    }
}

// ---------------------------------------------------------------------------
// Kernel 2: block-cooperative tiles. Block = 256 thr = 8 warps owning the 8
// ADJACENT features d = grp*8 .. grp*8+7, so one token's block-slice is 512B
// contiguous. The 64-token tile is loaded block-wide: warp w in round r
// handles token r*8+w, lane l carries float4 #l of that token's 512B row →
// every LDG/STG warp-instr covers 4 FULL 128B sectors (4 wf, was 8), and
// every STS/LDS warp-instr hits one pitch-132 row (conflict-free).
// Compute: warp w owns d = grp*8+w; lane l owns tokens l and l+32 (registers,
// FFMA2 contraction against smem-broadcast C). Output returns through the
// same tile (each lane overwrites exactly the cells it read).
// ---------------------------------------------------------------------------
__global__ void __launch_bounds__(256, 3)
siso_kernel(const float* __restrict__ state,
            const float* __restrict__ log_nA,
            const float* __restrict__ Bm,
            const float* __restrict__ Cm,
            float* __restrict__ out,
            int chunk_sz)
{
    extern __shared__ float sm[];
    float*  C_s   = sm + OFF_C;
    float2* AB_s  = reinterpret_cast<float2*>(sm + OFF_AB);
    float4* tile4 = reinterpret_cast<float4*>(sm + OFF_TILE);

    const int tid   = threadIdx.x;
    const int w     = tid >> 5;
    const int l     = tid & 31;
    const int grp   = blockIdx.x & 7;
    const int chunk = blockIdx.x >> 3;

    // stage C slice + (A*log2e, B) pairs
    {
        const float* src = Cm + grp * 8 * 256;
        for (int i = tid; i < 2048; i += 256) C_s[i] = src[i];
        if (tid < 128) {
            int dl = tid >> 4, n = tid & 15;
            int gd = grp * 8 + dl;
            float A2 = -__expf(log_nA[gd * 16 + n]) * LOG2E;
            AB_s[tid] = make_float2(A2, Bm[gd * 16 + n]);
        }
    }
    __syncthreads();

    const float2* ABw = AB_s + w * 16;
    const float*  Cw  = C_s + w * 256;
    const float*  dxb = g_dxT + (size_t)(grp * 8 + w) * VPAD;

    const float4* sg = reinterpret_cast<const float4*>(state) + grp * 32;
    float4*       og = reinterpret_cast<float4*>(out) + grp * 32;

    const int v_start = chunk * chunk_sz;
    const int v_end   = min(V_TOK, v_start + chunk_sz);

    for (int v0 = v_start; v0 < v_end; v0 += 64) {
        const int nt = min(64, v_end - v0);

        // ---- prefetch batch 1 + per-lane scalars (before sync) -------------
        float4 R0[4];
#pragma unroll
        for (int r = 0; r < 4; r++) {
            int tok = r * 8 + w;
            R0[r] = (tok < nt) ? sg[(size_t)(v0 + tok) * 256 + l]
                               : make_float4(0.f, 0.f, 0.f, 0.f);
        }
        const bool va = (l < nt);
        const bool vc = (l + 32 < nt);
        const float delta_a = va ? __ldg(&g_delta[v0 + l])      : 0.f;
        const float delta_c = vc ? __ldg(&g_delta[v0 + 32 + l]) : 0.f;
        const float dx_a    = va ? __ldg(&dxb[v0 + l])          : 0.f;
        const float dx_c    = vc ? __ldg(&dxb[v0 + 32 + l])     : 0.f;

        __syncthreads();   // S1: prior tile's STG reads are done

#pragma unroll
        for (int r = 0; r < 4; r++)
            tile4[(r * 8 + w) * PITCH4 + l] = R0[r];

        float4 R1[4];
#pragma unroll
        for (int r = 0; r < 4; r++) {
            int tok = (r + 4) * 8 + w;
            R1[r] = (tok < nt) ? sg[(size_t)(v0 + tok) * 256 + l]
                               : make_float4(0.f, 0.f, 0.f, 0.f);
        }
#pragma unroll
        for (int r = 0; r < 4; r++)
            tile4[((r + 4) * 8 + w) * PITCH4 + l] = R1[r];

        __syncthreads();   // S2: tile filled

        // ---- compute: lane owns tokens l and l+32 for feature d -------------
        const float* ra = sm + OFF_TILE + l * 132 + w * 16;
        const float* rb = sm + OFF_TILE + (l + 32) * 132 + w * 16;

        float2 acc_a[8], acc_c[8];
#pragma unroll
        for (int p = 0; p < 8; p++) {
            acc_a[p] = make_float2(0.f, 0.f);
            acc_c[p] = make_float2(0.f, 0.f);
        }

        float4 s4a, s4b;
#pragma unroll
        for (int n = 0; n < 16; n++) {
            if ((n & 3) == 0) {
                s4a = *reinterpret_cast<const float4*>(ra + n);
                s4b = *reinterpret_cast<const float4*>(rb + n);
            }
            float s_a = (n & 3) == 0 ? s4a.x : (n & 3) == 1 ? s4a.y : (n & 3) == 2 ? s4a.z : s4a.w;
            float s_c = (n & 3) == 0 ? s4b.x : (n & 3) == 1 ? s4b.y : (n & 3) == 2 ? s4b.z : s4b.w;

            float2 ab = ABw[n];
            float e_a = ex2_approx(delta_a * ab.x);
            float e_c = ex2_approx(delta_c * ab.x);
            float nv_a = fmaf(e_a, s_a, dx_a * ab.y);
            float nv_c = fmaf(e_c, s_c, dx_c * ab.y);
            float2 vva = make_float2(nv_a, nv_a);
            float2 vvc = make_float2(nv_c, nv_c);

            const float4* crow = reinterpret_cast<const float4*>(Cw + n * 16);
#pragma unroll
            for (int p4 = 0; p4 < 4; p4++) {
                float4 c4 = crow[p4];                      // broadcast LDS.128
                float2 c01 = make_float2(c4.x, c4.y);
                float2 c23 = make_float2(c4.z, c4.w);
                acc_a[2 * p4]     = ffma2(vva, c01, acc_a[2 * p4]);
                acc_a[2 * p4 + 1] = ffma2(vva, c23, acc_a[2 * p4 + 1]);
                acc_c[2 * p4]     = ffma2(vvc, c01, acc_c[2 * p4]);
                acc_c[2 * p4 + 1] = ffma2(vvc, c23, acc_c[2 * p4 + 1]);
            }
        }

        // ---- write results back into the SAME cells this lane read ---------
#pragma unroll
        for (int p4 = 0; p4 < 4; p4++) {
            tile4[l * PITCH4 + w * 4 + p4] =
                make_float4(acc_a[2 * p4].x, acc_a[2 * p4].y,
                            acc_a[2 * p4 + 1].x, acc_a[2 * p4 + 1].y);
            tile4[(l + 32) * PITCH4 + w * 4 + p4] =
                make_float4(acc_c[2 * p4].x, acc_c[2 * p4].y,
                            acc_c[2 * p4 + 1].x, acc_c[2 * p4 + 1].y);
        }

        __syncthreads();   // S3: out-tile complete

        // ---- block-wide coalesced store (full sectors) ----------------------
#pragma unroll
        for (int r = 0; r < 8; r++) {
            int tok = r * 8 + w;
            if (tok < nt)
                og[(size_t)(v0 + tok) * 256 + l] = tile4[tok * PITCH4 + l];
        }
    }
}

// ---------------------------------------------------------------------------
// Launch
// ---------------------------------------------------------------------------
extern "C" void kernel_launch(void* const* d_in, const int* in_sizes, int n_in,
                              void* d_out, int out_size)
{
    const float* x       = (const float*)d_in[0];  // [V, D]
    const float* state   = (const float*)d_in[1];  // [V, D, N]
    const float* log_nA  = (const float*)d_in[2];  // [D, N]
    const float* B       = (const float*)d_in[3];  // [D, N]
    const float* C       = (const float*)d_in[4];  // [D, N, N]
    const float* w_delta = (const float*)d_in[5];  // [1, D]
    const float* b_delta = (const float*)d_in[6];  // [1]
    float* out = (float*)d_out;                    // [V, D, N]

    // Kernel 1: delta + transposed dx
    delta_kernel<<<V_TOK / 32, 128>>>(x, w_delta, b_delta);

    // Kernel 2: 8 d-groups x 55 chunks = 440 blocks (3/SM target, 1 wave)
    const int n_chunks = 55;
    const int chunk_sz = 1856;                     // 29 tiles of 64
    const int smem_bytes = SMEM_FLOATS * 4;        // 43008 B

    cudaFuncSetAttribute(siso_kernel,
                         cudaFuncAttributeMaxDynamicSharedMemorySize, smem_bytes);
    siso_kernel<<<8 * n_chunks, 256, smem_bytes>>>(state, log_nA, B, C, out, chunk_sz);
}

// round 7
// speedup vs baseline: 1.7735x; 1.7735x over previous
#include <cuda_runtime.h>
#include <cstdint>

// DiagonalSISOCell: V=100000, D=64, N=16
// out[v,d,q] = sum_n ( exp(delta_v*A[d,n])*state[v,d,n] + delta_v*B[d,n]*x[v,d] ) * C[d,n,q]
// delta_v = softplus(x[v,:] @ w_delta + b_delta)

#define V_TOK 100000
#define VPAD  100224
#define LOG2E 1.4426950408889634f

__device__ float g_delta[VPAD];
__device__ float g_dxT[64 * VPAD];   // dxT[d][v] = delta_v * x[v,d]

// ---- per-warp smem layout (floats) ------------------------------------------
#define P4     9                     // float4 pitch of a token row (36 floats)
#define W_TILE (64 * 36)             // 2304: tile[64 tokens][32 floats + pad]
#define W_C    (2 * 272)             // 544: C padded per feature (272 ≡ 64B off)
#define W_AB   64                    // 2 features x 16 float2
#define WSZ    (W_TILE + W_C + W_AB) // 2912 floats = 11648 B per warp

// ---------------------------------------------------------------------------
__device__ __forceinline__ float2 ffma2(float2 a, float2 b, float2 c) {
    float2 r;
    asm("fma.rn.f32x2 %0, %1, %2, %3;"
        : "=l"(*reinterpret_cast<unsigned long long*>(&r))
        : "l"(*reinterpret_cast<unsigned long long*>(&a)),
          "l"(*reinterpret_cast<unsigned long long*>(&b)),
          "l"(*reinterpret_cast<unsigned long long*>(&c)));
    return r;
}
__device__ __forceinline__ float ex2_approx(float x) {
    float r; asm("ex2.approx.f32 %0, %1;" : "=f"(r) : "f"(x)); return r;
}

// ---------------------------------------------------------------------------
// Kernel 1: per 32-token block — delta[v] (softplus) and transposed
// dxT[d][v] = delta_v * x[v,d], coalesced reads AND writes.
// ---------------------------------------------------------------------------
__global__ void __launch_bounds__(128)
delta_kernel(const float* __restrict__ x,
             const float* __restrict__ w,
             const float* __restrict__ b)
{
    __shared__ float xs[32 * 65];
    __shared__ float ws[64];
    __shared__ float ds[32];

    const int tid = threadIdx.x;
    const int v0  = blockIdx.x * 32;

    if (tid < 64) ws[tid] = w[tid];

#pragma unroll
    for (int j = 0; j < 16; j++) {
        int idx = j * 128 + tid;
        int row = idx >> 6, col = idx & 63;
        xs[row * 65 + col] = x[(size_t)v0 * 64 + idx];
    }
    __syncthreads();

    {
        int t = tid >> 2, sub = tid & 3;
        float s = 0.f;
        const float* xr = xs + t * 65 + sub * 16;
        const float* wr = ws + sub * 16;
#pragma unroll
        for (int k = 0; k < 16; k++) s = fmaf(xr[k], wr[k], s);
        s += __shfl_xor_sync(0xffffffffu, s, 1);
        s += __shfl_xor_sync(0xffffffffu, s, 2);
        if (sub == 0) {
            float tt = s + b[0];
            ds[t] = fmaxf(tt, 0.0f) + log1pf(expf(-fabsf(tt)));
        }
    }
    __syncthreads();

    if (tid < 32) g_delta[v0 + tid] = ds[tid];

#pragma unroll
    for (int j = 0; j < 16; j++) {
        int d = j * 4 + (tid >> 5);
        int t = tid & 31;
        g_dxT[(size_t)d * VPAD + v0 + t] = ds[t] * xs[t * 65 + d];
    }
}

// ---------------------------------------------------------------------------
// Kernel 2: warp-independent d-PAIR tiles (only __syncwarp in the hot loop).
// Warp owns features (2*dpair, 2*dpair+1): one token's slice is 128B
// contiguous, so each LDG/STG.128 covers 4 FULL sectors. 64-token tile lives
// in a pitch-36 smem buffer (in-place in/out). Compute: lane = (fs=l>>4,
// q=l&15) owns 4 tokens (q+16j) of feature d=2*dpair+fs -> C rows amortize
// over 4 tokens; exp once per (v,d,n); FFMA2 contraction.
// ---------------------------------------------------------------------------
__global__ void __launch_bounds__(128, 4)
siso_kernel(const float* __restrict__ state,
            const float* __restrict__ log_nA,
            const float* __restrict__ Bm,
            const float* __restrict__ Cm,
            float* __restrict__ out,
            int chunk_sz)
{
    extern __shared__ float sm[];
    const int tid   = threadIdx.x;
    const int w     = tid >> 5;
    const int l     = tid & 31;
    const int grp   = blockIdx.x & 7;     // 8 dpair-groups of 4 warps
    const int chunk = blockIdx.x >> 3;
    const int dpair = grp * 4 + w;

    float*  W     = sm + w * WSZ;
    float4* tile4 = reinterpret_cast<float4*>(W);
    float*  Cws   = W + W_TILE;
    float2* ABws  = reinterpret_cast<float2*>(W + W_TILE + W_C);

    // --- per-warp init: C (padded 272/feature) + (A*log2e, B) ---------------
    {
        const float* src = Cm + dpair * 512;
#pragma unroll
        for (int k = 0; k < 16; k++) {
            int idx = k * 32 + l;
            Cws[(idx >> 8) * 272 + (idx & 255)] = src[idx];
        }
        int f = l >> 4, n = l & 15;
        int dd = dpair * 2 + f;
        float A2 = -__expf(log_nA[dd * 16 + n]) * LOG2E;
        ABws[l] = make_float2(A2, Bm[dd * 16 + n]);
    }
    __syncwarp();

    const int fs = l >> 4;          // feature sub-index
    const int q  = l & 15;          // base token within 16-group
    const int f4 = l & 7;           // loader float4 index within 128B row
    const int tb = l >> 3;          // loader token sub-index (0..3)
    const int d  = dpair * 2 + fs;

    const float2* ABl = ABws + fs * 16;
    const float*  Cf  = Cws + fs * 272;
    const float*  dxr = g_dxT + (size_t)d * VPAD;

    const float4* sg = reinterpret_cast<const float4*>(state) + dpair * 8 + f4;
    float4*       og = reinterpret_cast<float4*>(out)        + dpair * 8 + f4;

    const int v_start = chunk * chunk_sz;
    if (v_start >= V_TOK) return;
    const int v_end = min(V_TOK, v_start + chunk_sz);

    for (int v0 = v_start; v0 < v_end; v0 += 64) {
        const int nt = min(64, v_end - v0);

        // ---- LDG: 16 instrs, 4 full 128B sectors each ----------------------
        float4 R[16];
#pragma unroll
        for (int i = 0; i < 16; i++) {
            int t = 4 * i + tb;
            R[i] = (t < nt) ? sg[(size_t)(v0 + t) * 256]
                            : make_float4(0.f, 0.f, 0.f, 0.f);
        }
        // per-lane token scalars (contiguous, 1-2 sectors per instr)
        float dlt[4], dxv[4];
#pragma unroll
        for (int j = 0; j < 4; j++) {
            int t = q + 16 * j;
            bool vv = (t < nt);
            dlt[j] = vv ? __ldg(&g_delta[v0 + t]) : 0.f;
            dxv[j] = vv ? __ldg(&dxr[v0 + t])     : 0.f;
        }

        __syncwarp();   // prior tile's LDS-out complete
#pragma unroll
        for (int i = 0; i < 16; i++) {
            int t = 4 * i + tb;
            tile4[t * P4 + f4] = R[i];
        }
        __syncwarp();   // tile filled

        // ---- compute: 4 tokens per lane ------------------------------------
        float2 acc[4][8];
#pragma unroll
        for (int j = 0; j < 4; j++)
#pragma unroll
            for (int p = 0; p < 8; p++) acc[j][p] = make_float2(0.f, 0.f);

        float4 s4[4];
#pragma unroll
        for (int n = 0; n < 16; n++) {
            if ((n & 3) == 0) {
#pragma unroll
                for (int j = 0; j < 4; j++)
                    s4[j] = tile4[(q + 16 * j) * P4 + fs * 4 + (n >> 2)];
            }
            const float2 ab = ABl[n];
            const float4* crow = reinterpret_cast<const float4*>(Cf + n * 16);
            float4 ca = crow[0], cb = crow[1], cc = crow[2], cd = crow[3];
            float2 c0 = make_float2(ca.x, ca.y), c1 = make_float2(ca.z, ca.w);
            float2 c2 = make_float2(cb.x, cb.y), c3 = make_float2(cb.z, cb.w);
            float2 c4 = make_float2(cc.x, cc.y), c5 = make_float2(cc.z, cc.w);
            float2 c6 = make_float2(cd.x, cd.y), c7 = make_float2(cd.z, cd.w);

#pragma unroll
            for (int j = 0; j < 4; j++) {
                float s = (n & 3) == 0 ? s4[j].x : (n & 3) == 1 ? s4[j].y
                        : (n & 3) == 2 ? s4[j].z : s4[j].w;
                float e  = ex2_approx(dlt[j] * ab.x);
                float nv = fmaf(e, s, dxv[j] * ab.y);
                float2 nv2 = make_float2(nv, nv);
                acc[j][0] = ffma2(nv2, c0, acc[j][0]);
                acc[j][1] = ffma2(nv2, c1, acc[j][1]);
                acc[j][2] = ffma2(nv2, c2, acc[j][2]);
                acc[j][3] = ffma2(nv2, c3, acc[j][3]);
                acc[j][4] = ffma2(nv2, c4, acc[j][4]);
                acc[j][5] = ffma2(nv2, c5, acc[j][5]);
                acc[j][6] = ffma2(nv2, c6, acc[j][6]);
                acc[j][7] = ffma2(nv2, c7, acc[j][7]);
            }
        }

        // ---- STS-out: each lane overwrites exactly the cells it read -------
#pragma unroll
        for (int j = 0; j < 4; j++)
#pragma unroll
            for (int p = 0; p < 4; p++)
                tile4[(q + 16 * j) * P4 + fs * 4 + p] =
                    make_float4(acc[j][2 * p].x,     acc[j][2 * p].y,
                                acc[j][2 * p + 1].x, acc[j][2 * p + 1].y);
        __syncwarp();   // out-tile complete

        // ---- LDS-out + STG: full sectors ------------------------------------
#pragma unroll
        for (int i = 0; i < 16; i++) {
            int t = 4 * i + tb;
            float4 vo = tile4[t * P4 + f4];
            if (t < nt) og[(size_t)(v0 + t) * 256] = vo;
        }
    }
}

// ---------------------------------------------------------------------------
// Launch
// ---------------------------------------------------------------------------
extern "C" void kernel_launch(void* const* d_in, const int* in_sizes, int n_in,
                              void* d_out, int out_size)
{
    const float* x       = (const float*)d_in[0];  // [V, D]
    const float* state   = (const float*)d_in[1];  // [V, D, N]
    const float* log_nA  = (const float*)d_in[2];  // [D, N]
    const float* B       = (const float*)d_in[3];  // [D, N]
    const float* C       = (const float*)d_in[4];  // [D, N, N]
    const float* w_delta = (const float*)d_in[5];  // [1, D]
    const float* b_delta = (const float*)d_in[6];  // [1]
    float* out = (float*)d_out;                    // [V, D, N]

    // Kernel 1: delta + transposed dx
    delta_kernel<<<V_TOK / 32, 128>>>(x, w_delta, b_delta);

    // Kernel 2: 8 dpair-groups x 72 chunks = 576 blocks (4/SM, ~1 wave)
    const int n_chunks = 72;
    const int chunk_sz = 1408;                     // 22 tiles of 64
    const int smem_bytes = 4 * WSZ * 4;            // 46592 B per block

    cudaFuncSetAttribute(siso_kernel,
                         cudaFuncAttributeMaxDynamicSharedMemorySize, smem_bytes);
    siso_kernel<<<8 * n_chunks, 128, smem_bytes>>>(state, log_nA, B, C, out, chunk_sz);
}

// round 8
// speedup vs baseline: 1.9311x; 1.0889x over previous
#include <cuda_runtime.h>
#include <cstdint>

// DiagonalSISOCell: V=100000, D=64, N=16
// out[v,d,q] = sum_n ( exp(delta_v*A[d,n])*state[v,d,n] + delta_v*B[d,n]*x[v,d] ) * C[d,n,q]
// delta_v = softplus(x[v,:] @ w_delta + b_delta)

#define V_TOK 100000
#define VPAD  100224
#define LOG2E 1.4426950408889634f

__device__ float g_delta[VPAD];
__device__ float g_dxT[64 * VPAD];   // dxT[d][v] = delta_v * x[v,d]

// ---- per-warp smem layout (floats) ------------------------------------------
#define TILE_T 48                    // tokens per tile (J = 3 per lane)
#define P4     9                     // float4 pitch of a token row (36 floats)
#define W_T1   (TILE_T * 36)         // 1728 floats per tile buffer
#define W_C    (2 * 272)             // C padded per feature
#define W_AB   64
#define WSZ    (2 * W_T1 + W_C + W_AB)   // 4064 floats = 16256 B per warp

// ---------------------------------------------------------------------------
__device__ __forceinline__ float2 ffma2(float2 a, float2 b, float2 c) {
    float2 r;
    asm("fma.rn.f32x2 %0, %1, %2, %3;"
        : "=l"(*reinterpret_cast<unsigned long long*>(&r))
        : "l"(*reinterpret_cast<unsigned long long*>(&a)),
          "l"(*reinterpret_cast<unsigned long long*>(&b)),
          "l"(*reinterpret_cast<unsigned long long*>(&c)));
    return r;
}
__device__ __forceinline__ float ex2_approx(float x) {
    float r; asm("ex2.approx.f32 %0, %1;" : "=f"(r) : "f"(x)); return r;
}
__device__ __forceinline__ uint32_t smem_u32(const void* p) {
    uint32_t a;
    asm("{ .reg .u64 t; cvta.to.shared.u64 t, %1; cvt.u32.u64 %0, t; }"
        : "=r"(a) : "l"(p));
    return a;
}
__device__ __forceinline__ void cp16(uint32_t dst, const void* src) {
    asm volatile("cp.async.cg.shared.global [%0], [%1], 16;"
                 :: "r"(dst), "l"(src) : "memory");
}
__device__ __forceinline__ void cp_commit() {
    asm volatile("cp.async.commit_group;" ::: "memory");
}
__device__ __forceinline__ void cp_wait1() {
    asm volatile("cp.async.wait_group 1;" ::: "memory");
}

// ---------------------------------------------------------------------------
// Kernel 1: per 32-token block — delta[v] (softplus) and transposed
// dxT[d][v] = delta_v * x[v,d], coalesced reads AND writes.
// ---------------------------------------------------------------------------
__global__ void __launch_bounds__(128)
delta_kernel(const float* __restrict__ x,
             const float* __restrict__ w,
             const float* __restrict__ b)
{
    __shared__ float xs[32 * 65];
    __shared__ float ws[64];
    __shared__ float ds[32];

    const int tid = threadIdx.x;
    const int v0  = blockIdx.x * 32;

    if (tid < 64) ws[tid] = w[tid];

#pragma unroll
    for (int j = 0; j < 16; j++) {
        int idx = j * 128 + tid;
        int row = idx >> 6, col = idx & 63;
        xs[row * 65 + col] = x[(size_t)v0 * 64 + idx];
    }
    __syncthreads();

    {
        int t = tid >> 2, sub = tid & 3;
        float s = 0.f;
        const float* xr = xs + t * 65 + sub * 16;
        const float* wr = ws + sub * 16;
#pragma unroll
        for (int k = 0; k < 16; k++) s = fmaf(xr[k], wr[k], s);
        s += __shfl_xor_sync(0xffffffffu, s, 1);
        s += __shfl_xor_sync(0xffffffffu, s, 2);
        if (sub == 0) {
            float tt = s + b[0];
            ds[t] = fmaxf(tt, 0.0f) + log1pf(expf(-fabsf(tt)));
        }
    }
    __syncthreads();

    if (tid < 32) g_delta[v0 + tid] = ds[tid];

#pragma unroll
    for (int j = 0; j < 16; j++) {
        int d = j * 4 + (tid >> 5);
        int t = tid & 31;
        g_dxT[(size_t)d * VPAD + v0 + t] = ds[t] * xs[t * 65 + d];
    }
}

// ---------------------------------------------------------------------------
// Kernel 2: warp-independent d-PAIR tiles, double-buffered via cp.async.
// Warp owns features (2*dpair, 2*dpair+1) -> 128B/token rows, full sectors.
// 48-token tiles: buf(i) computed while buf(i+1) streams in (cp.async.cg,
// zero register staging). Lane = (fs=l>>4, q=l&15) owns tokens q+16j, j<3.
// Only __syncwarp in the hot loop.
// ---------------------------------------------------------------------------
__global__ void __launch_bounds__(128, 3)
siso_kernel(const float* __restrict__ state,
            const float* __restrict__ log_nA,
            const float* __restrict__ Bm,
            const float* __restrict__ Cm,
            float* __restrict__ out,
            int chunk_sz)
{
    extern __shared__ float sm[];
    const int tid   = threadIdx.x;
    const int w     = tid >> 5;
    const int l     = tid & 31;
    const int grp   = blockIdx.x & 7;     // 8 dpair-groups of 4 warps
    const int chunk = blockIdx.x >> 3;
    const int dpair = grp * 4 + w;

    float*   W     = sm + w * WSZ;
    float4*  tile4 = reinterpret_cast<float4*>(W);          // [2][432] float4
    float*   Cws   = W + 2 * W_T1;
    float2*  ABws  = reinterpret_cast<float2*>(W + 2 * W_T1 + W_C);
    const uint32_t Wb = smem_u32(W);                         // byte addr of W

    // --- per-warp init: C (padded 272/feature) + (A*log2e, B) ---------------
    {
        const float* src = Cm + dpair * 512;
#pragma unroll
        for (int k = 0; k < 16; k++) {
            int idx = k * 32 + l;
            Cws[(idx >> 8) * 272 + (idx & 255)] = src[idx];
        }
        int f = l >> 4, n = l & 15;
        int dd = dpair * 2 + f;
        float A2 = -__expf(log_nA[dd * 16 + n]) * LOG2E;
        ABws[l] = make_float2(A2, Bm[dd * 16 + n]);
    }

    const int fs = l >> 4;          // feature sub-index
    const int q  = l & 15;          // base token within 16-group
    const int f4 = l & 7;           // loader float4 index within 128B row
    const int tb = l >> 3;          // loader token sub-index (0..3)
    const int d  = dpair * 2 + fs;

    const float2* ABl = ABws + fs * 16;
    const float*  Cf  = Cws + fs * 272;
    const float*  dxr = g_dxT + (size_t)d * VPAD;

    const char* sg_b = reinterpret_cast<const char*>(state) + dpair * 128 + f4 * 16;
    float4*     og   = reinterpret_cast<float4*>(out) + dpair * 8 + f4;

    const int v_start = chunk * chunk_sz;
    if (v_start >= V_TOK) return;
    const int v_end   = min(V_TOK, v_start + chunk_sz);
    const int n_tiles = (v_end - v_start + TILE_T - 1) / TILE_T;

    // issue cp.async for tile ti into buffer b (12 x 16B per lane)
    auto issue = [&](int ti, int b) {
        if (ti < n_tiles) {
            const int v0 = v_start + ti * TILE_T;
            const int nt = min(TILE_T, v_end - v0);
            const uint32_t dst0 = Wb + (uint32_t)(b * W_T1 + f4 * 4) * 4;
            const char* src0 = sg_b + (size_t)v0 * 4096;
#pragma unroll
            for (int i = 0; i < 12; i++) {
                int t = 4 * i + tb;
                if (t < nt)
                    cp16(dst0 + (uint32_t)t * 144, src0 + (size_t)t * 4096);
            }
        }
        cp_commit();
    };

    issue(0, 0);
    issue(1, 1);

    for (int i = 0; i < n_tiles; i++) {
        const int b  = i & 1;
        const int v0 = v_start + i * TILE_T;
        const int nt = min(TILE_T, v_end - v0);
        const float4* tb4 = tile4 + b * (W_T1 / 4);
        float4*       tw4 = tile4 + b * (W_T1 / 4);

        // per-lane token scalars (issue before the wait to overlap)
        float dlt[3], dxv[3];
#pragma unroll
        for (int j = 0; j < 3; j++) {
            int t = q + 16 * j;
            bool vv = (t < nt);
            dlt[j] = vv ? __ldg(&g_delta[v0 + t]) : 0.f;
            dxv[j] = vv ? __ldg(&dxr[v0 + t])     : 0.f;
        }

        cp_wait1();      // tile i resident (tile i+1 may still be in flight)
        __syncwarp();    // all lanes' copies for buf b complete

        // ---- compute: 3 tokens per lane ------------------------------------
        float2 acc[3][8];
#pragma unroll
        for (int j = 0; j < 3; j++)
#pragma unroll
            for (int p = 0; p < 8; p++) acc[j][p] = make_float2(0.f, 0.f);

        float4 s4[3];
#pragma unroll
        for (int n = 0; n < 16; n++) {
            if ((n & 3) == 0) {
#pragma unroll
                for (int j = 0; j < 3; j++)
                    s4[j] = tb4[(q + 16 * j) * P4 + fs * 4 + (n >> 2)];
            }
            const float2 ab = ABl[n];
            const float4* crow = reinterpret_cast<const float4*>(Cf + n * 16);
            float4 ca = crow[0], cb = crow[1], cc = crow[2], cd = crow[3];
            float2 c0 = make_float2(ca.x, ca.y), c1 = make_float2(ca.z, ca.w);
            float2 c2 = make_float2(cb.x, cb.y), c3 = make_float2(cb.z, cb.w);
            float2 c4 = make_float2(cc.x, cc.y), c5 = make_float2(cc.z, cc.w);
            float2 c6 = make_float2(cd.x, cd.y), c7 = make_float2(cd.z, cd.w);

#pragma unroll
            for (int j = 0; j < 3; j++) {
                float s = (n & 3) == 0 ? s4[j].x : (n & 3) == 1 ? s4[j].y
                        : (n & 3) == 2 ? s4[j].z : s4[j].w;
                float e  = ex2_approx(dlt[j] * ab.x);
                float nv = fmaf(e, s, dxv[j] * ab.y);
                float2 nv2 = make_float2(nv, nv);
                acc[j][0] = ffma2(nv2, c0, acc[j][0]);
                acc[j][1] = ffma2(nv2, c1, acc[j][1]);
                acc[j][2] = ffma2(nv2, c2, acc[j][2]);
                acc[j][3] = ffma2(nv2, c3, acc[j][3]);
                acc[j][4] = ffma2(nv2, c4, acc[j][4]);
                acc[j][5] = ffma2(nv2, c5, acc[j][5]);
                acc[j][6] = ffma2(nv2, c6, acc[j][6]);
                acc[j][7] = ffma2(nv2, c7, acc[j][7]);
            }
        }

        // ---- STS-out: each lane overwrites exactly the cells it read -------
#pragma unroll
        for (int j = 0; j < 3; j++)
#pragma unroll
            for (int p = 0; p < 4; p++)
                tw4[(q + 16 * j) * P4 + fs * 4 + p] =
                    make_float4(acc[j][2 * p].x,     acc[j][2 * p].y,
                                acc[j][2 * p + 1].x, acc[j][2 * p + 1].y);
        __syncwarp();   // out-tile complete

        // ---- LDS-out + STG: full sectors ------------------------------------
#pragma unroll
        for (int i2 = 0; i2 < 12; i2++) {
            int t = 4 * i2 + tb;
            float4 vo = tb4[t * P4 + f4];
            if (t < nt) og[(size_t)(v0 + t) * 256] = vo;
        }
        __syncwarp();   // buf b free (LDS reads drained well before cp lands)

        issue(i + 2, b);  // refill this buffer
    }
}

// ---------------------------------------------------------------------------
// Launch
// ---------------------------------------------------------------------------
extern "C" void kernel_launch(void* const* d_in, const int* in_sizes, int n_in,
                              void* d_out, int out_size)
{
    const float* x       = (const float*)d_in[0];  // [V, D]
    const float* state   = (const float*)d_in[1];  // [V, D, N]
    const float* log_nA  = (const float*)d_in[2];  // [D, N]
    const float* B       = (const float*)d_in[3];  // [D, N]
    const float* C       = (const float*)d_in[4];  // [D, N, N]
    const float* w_delta = (const float*)d_in[5];  // [1, D]
    const float* b_delta = (const float*)d_in[6];  // [1]
    float* out = (float*)d_out;                    // [V, D, N]

    // Kernel 1: delta + transposed dx
    delta_kernel<<<V_TOK / 32, 128>>>(x, w_delta, b_delta);

    // Kernel 2: 8 dpair-groups x 55 chunks = 440 blocks (3/SM, ~1 wave)
    const int n_chunks = 55;
    const int chunk_sz = 1824;                     // 38 tiles of 48
    const int smem_bytes = 4 * WSZ * 4;            // 65024 B per block

    cudaFuncSetAttribute(siso_kernel,
                         cudaFuncAttributeMaxDynamicSharedMemorySize, smem_bytes);
    siso_kernel<<<8 * n_chunks, 128, smem_bytes>>>(state, log_nA, B, C, out, chunk_sz);
}